// round 2
// baseline (speedup 1.0000x reference)
#include <cuda_runtime.h>
#include <cuda_bf16.h>
#include <math.h>

// ---------------- problem constants ----------------
#define TT      8192          // sequence length
#define DIN     1728          // conv feature dim
#define HID     512
#define GATES   2048          // 4*HID
#define Y1DIM   1024          // 2*HID
#define TAGS    27
#define STARTT  25
#define STOPT   26

// recurrence partitioning
#define RC_C    32            // CTAs per direction
#define RC_U    16            // hidden units per CTA (512/32)
#define RC_ROWS 64            // gate rows per CTA (4*RC_U)

// ---------------- device scratch ----------------
__device__ float d_x   [TT * DIN];       // conv output features
__device__ float d_gxf [TT * GATES];     // precomputed input gates, fwd
__device__ float d_gxr [TT * GATES];     // precomputed input gates, bwd
__device__ float d_y0  [TT * Y1DIM];     // layer0 output (fwd | bwd)
__device__ float d_y1  [TT * Y1DIM];     // layer1 output
__device__ float d_logits[TT * 32];      // tag logits (stride 32, 27 used)
__device__ int   d_progress[2 * RC_C];   // per-CTA step counters

// ---------------- conv feature kernel ----------------
__global__ void conv_kernel(const float* __restrict__ F,
                            const float* __restrict__ W1, const float* __restrict__ B1,
                            const float* __restrict__ W3, const float* __restrict__ B3,
                            const float* __restrict__ W5, const float* __restrict__ B5,
                            float* __restrict__ X)
{
    int t = blockIdx.x;
    __shared__ float fsh[448];
    __shared__ float w1s[448];
    __shared__ float w3s[768];
    __shared__ float w5s[1280];
    __shared__ float b1s[16], b3s[16], b5s[16];
    int tid = threadIdx.x;   // 128 threads

    for (int i = tid; i < 448;  i += 128) fsh[i] = F[t * 448 + i];
    for (int i = tid; i < 448;  i += 128) w1s[i] = W1[i];
    for (int i = tid; i < 768;  i += 128) w3s[i] = W3[i];
    for (int i = tid; i < 1280; i += 128) w5s[i] = W5[i];
    if (tid < 16) { b1s[tid] = B1[tid]; b3s[tid] = B3[tid]; b5s[tid] = B5[tid]; }
    __syncthreads();

    for (int idx = tid; idx < DIN; idx += 128) {
        float acc;
        if (idx < 192) {
            int c = idx / 12, w = idx % 12;
            acc = b1s[c];
            #pragma unroll
            for (int kh = 0; kh < 7; kh++)
                #pragma unroll
                for (int kw = 0; kw < 4; kw++)
                    acc = fmaf(fsh[kh * 64 + w * 4 + kw], w1s[c * 28 + kh * 4 + kw], acc);
        } else if (idx < 960) {
            int j = idx - 192;
            int c = j / 48, r = j % 48, h = r / 12, w = r % 12;
            acc = b3s[c];
            #pragma unroll
            for (int kh = 0; kh < 4; kh++)
                #pragma unroll
                for (int kw = 0; kw < 12; kw++)
                    acc = fmaf(fsh[(h + kh) * 64 + w * 4 + kw], w3s[c * 48 + kh * 12 + kw], acc);
        } else {
            int j = idx - 960;
            int c = j / 48, r = j % 48, h = r / 12, w = r % 12;
            acc = b5s[c];
            #pragma unroll
            for (int kh = 0; kh < 4; kh++)
                #pragma unroll
                for (int kw = 0; kw < 20; kw++)
                    acc = fmaf(fsh[(h + kh) * 64 + w * 4 + kw], w5s[c * 80 + kh * 20 + kw], acc);
        }
        X[(size_t)t * DIN + idx] = acc;
    }
}

// ---------------- fp32 tiled GEMM: C[M,N] = A[M,K] @ B[N,K]^T + b1[n] + b2[n] ----------------
__global__ __launch_bounds__(256) void gemm128_kernel(
    const float* __restrict__ A, const float* __restrict__ B,
    const float* __restrict__ bias1, const float* __restrict__ bias2,
    float* __restrict__ C, int M, int N, int K)
{
    __shared__ float As[16][128];
    __shared__ float Bs[16][128];
    const int tid = threadIdx.x;
    const int m0 = blockIdx.y * 128;
    const int n0 = blockIdx.x * 128;
    const int tx = tid & 15;
    const int ty = tid >> 4;

    float acc[8][8];
    #pragma unroll
    for (int i = 0; i < 8; i++)
        #pragma unroll
        for (int j = 0; j < 8; j++) acc[i][j] = 0.f;

    for (int k0 = 0; k0 < K; k0 += 16) {
        #pragma unroll
        for (int i = 0; i < 2; i++) {
            int id  = tid + i * 256;
            int row = id >> 2;
            int kq  = (id & 3) * 4;
            float4 va = *(const float4*)(A + (size_t)(m0 + row) * K + k0 + kq);
            As[kq + 0][row] = va.x; As[kq + 1][row] = va.y;
            As[kq + 2][row] = va.z; As[kq + 3][row] = va.w;
            float4 vb = *(const float4*)(B + (size_t)(n0 + row) * K + k0 + kq);
            Bs[kq + 0][row] = vb.x; Bs[kq + 1][row] = vb.y;
            Bs[kq + 2][row] = vb.z; Bs[kq + 3][row] = vb.w;
        }
        __syncthreads();
        #pragma unroll
        for (int k = 0; k < 16; k++) {
            float a[8], b[8];
            #pragma unroll
            for (int i = 0; i < 8; i++) a[i] = As[k][ty * 8 + i];
            #pragma unroll
            for (int j = 0; j < 8; j++) b[j] = Bs[k][tx * 8 + j];
            #pragma unroll
            for (int i = 0; i < 8; i++)
                #pragma unroll
                for (int j = 0; j < 8; j++)
                    acc[i][j] = fmaf(a[i], b[j], acc[i][j]);
        }
        __syncthreads();
    }

    #pragma unroll
    for (int i = 0; i < 8; i++) {
        int m = m0 + ty * 8 + i;
        #pragma unroll
        for (int j = 0; j < 8; j++) {
            int n = n0 + tx * 8 + j;
            C[(size_t)m * N + n] = acc[i][j] + bias1[n] + bias2[n];
        }
    }
}

// ---------------- progress reset ----------------
__global__ void zero_progress_kernel()
{
    if (threadIdx.x < 2 * RC_C) d_progress[threadIdx.x] = 0;
}

// ---------------- persistent bidirectional LSTM recurrence ----------------
// grid = 64 CTAs: blocks [0,32) forward, [32,64) backward, 256 threads each.
// Each CTA owns RC_U hidden units; its 64 x 512 Whh slice is held in registers.
__device__ __forceinline__ float sigm(float x) { return 1.f / (1.f + expf(-x)); }

__global__ __launch_bounds__(256, 1) void recur_kernel(
    const float* __restrict__ gx_f, const float* __restrict__ gx_r,
    const float* __restrict__ whh_f, const float* __restrict__ whh_r,
    float* __restrict__ y)
{
    const int dir = blockIdx.x >> 5;          // 0 fwd, 1 bwd
    const int cta = blockIdx.x & 31;
    const float* __restrict__ gx  = dir ? gx_r  : gx_f;
    const float* __restrict__ whh = dir ? whh_r : whh_f;
    const int u0  = cta * RC_U;
    const int tid = threadIdx.x;
    const int warp = tid >> 5, lane = tid & 31;
    const int kq = warp & 3;                  // k-quarter (128 k each)
    const int rg = warp >> 2;                 // row group (32 rows each)
    const int lr = rg * 32 + lane;            // local gate row 0..63
    const int gate = lr >> 4, uu = lr & 15;
    const int grow = gate * 512 + u0 + uu;    // global gate row in Whh / gx
    const int kbase = kq * 128;

    __shared__ float hsh[512];
    __shared__ float red[4][64];
    __shared__ float gsh[64];

    // one-time: Whh slice into registers (128 floats / thread)
    float w[128];
    {
        const float4* wp = (const float4*)(whh + (size_t)grow * 512 + kbase);
        #pragma unroll
        for (int j = 0; j < 32; j++) {
            float4 v = wp[j];
            w[4 * j + 0] = v.x; w[4 * j + 1] = v.y;
            w[4 * j + 2] = v.z; w[4 * j + 3] = v.w;
        }
    }

    float c_state = 0.f;   // live in threads 0..15
    volatile int* vprog = d_progress;

    for (int s = 0; s < TT; s++) {
        const int tt = dir ? (TT - 1 - s) : s;

        // prefetch this step's gx contribution (independent of h)
        float gxv = 0.f;
        if (tid < 64) {
            int g2 = (tid >> 4) * 512 + u0 + (tid & 15);
            gxv = gx[(size_t)tt * GATES + g2];
        }

        if (s > 0) {
            // wait for all producer CTAs of this direction to finish step s-1
            if (tid < RC_C) {
                int idx = dir * RC_C + tid;
                while (vprog[idx] < s) { }
            }
            __threadfence();      // acquire
            __syncthreads();

            // gather full h_{s-1} into shared
            const int tprev = dir ? (tt + 1) : (tt - 1);
            const float* hp = y + (size_t)tprev * Y1DIM + dir * HID;
            hsh[tid]       = hp[tid];
            hsh[tid + 256] = hp[tid + 256];
            __syncthreads();

            // matvec: each thread 128 MACs over its register-resident weights
            float acc = 0.f;
            #pragma unroll
            for (int j = 0; j < 32; j++) {
                float4 hv = *(const float4*)&hsh[kbase + 4 * j];
                acc = fmaf(w[4 * j + 0], hv.x, acc);
                acc = fmaf(w[4 * j + 1], hv.y, acc);
                acc = fmaf(w[4 * j + 2], hv.z, acc);
                acc = fmaf(w[4 * j + 3], hv.w, acc);
            }
            red[kq][lr] = acc;
            __syncthreads();
        } else {
            if (tid < 64) { red[0][tid] = 0.f; red[1][tid] = 0.f; red[2][tid] = 0.f; red[3][tid] = 0.f; }
            __syncthreads();
        }

        // reduce 4 k-partials, add gx
        if (tid < 64)
            gsh[tid] = red[0][tid] + red[1][tid] + red[2][tid] + red[3][tid] + gxv;
        __syncthreads();

        // gate nonlinearities + state update (threads 0..15 own the units)
        if (tid < 16) {
            float gi = gsh[tid];
            float gf = gsh[16 + tid];
            float gg = gsh[32 + tid];
            float go = gsh[48 + tid];
            c_state = sigm(gf) * c_state + sigm(gi) * tanhf(gg);
            float h = sigm(go) * tanhf(c_state);
            y[(size_t)tt * Y1DIM + dir * HID + u0 + tid] = h;
        }

        __threadfence();          // release: make h visible GPU-wide
        __syncthreads();
        if (tid == 0) {
            // relaxed store is fine after the fence+barrier above
            d_progress[dir * RC_C + cta] = s + 1;
            __threadfence();
        }
    }
}

// ---------------- tag head: logits = y1 @ h2t_w^T + b ----------------
__global__ void h2t_kernel(const float* __restrict__ Y, const float* __restrict__ W,
                           const float* __restrict__ B, float* __restrict__ L)
{
    int id = blockIdx.x * blockDim.x + threadIdx.x;
    int t = id >> 5;
    int n = id & 31;
    if (t >= TT || n >= TAGS) return;
    const float4* yr = (const float4*)(Y + (size_t)t * Y1DIM);
    const float4* wr = (const float4*)(W + (size_t)n * Y1DIM);
    float acc = 0.f;
    #pragma unroll 8
    for (int k = 0; k < Y1DIM / 4; k++) {
        float4 a = yr[k], b = wr[k];
        acc = fmaf(a.x, b.x, acc);
        acc = fmaf(a.y, b.y, acc);
        acc = fmaf(a.z, b.z, acc);
        acc = fmaf(a.w, b.w, acc);
    }
    L[t * 32 + n] = acc + B[n];
}

// ---------------- Viterbi (single warp, backpointers in SMEM) ----------------
__global__ void viterbi_kernel(const float* __restrict__ L, const float* __restrict__ trans,
                               float* __restrict__ out, int out_size)
{
    extern __shared__ unsigned char sm[];
    unsigned char* bp = sm;                              // TT * TAGS bytes
    float* fvs = (float*)(sm + TT * TAGS);               // 27 floats (221184 % 4 == 0)
    const int lane = threadIdx.x;

    float tr[TAGS];
    if (lane < TAGS) {
        #pragma unroll
        for (int p = 0; p < TAGS; p++) tr[p] = trans[lane * TAGS + p];
        fvs[lane] = (lane == STARTT) ? 0.f : -10000.f;
    }
    __syncwarp();

    for (int t = 0; t < TT; t++) {
        float feat = (lane < TAGS) ? L[t * 32 + lane] : 0.f;
        float best = -3.4e38f;
        int arg = 0;
        if (lane < TAGS) {
            #pragma unroll
            for (int p = 0; p < TAGS; p++) {
                float s = fvs[p] + tr[p];
                if (s > best) { best = s; arg = p; }
            }
        }
        __syncwarp();
        if (lane < TAGS) {
            fvs[lane] = best + feat;
            bp[t * TAGS + lane] = (unsigned char)arg;
        }
        __syncwarp();
    }

    float term = (lane < TAGS) ? fvs[lane] + trans[STOPT * TAGS + lane] : -3.4e38f;
    int bi = lane;
    #pragma unroll
    for (int off = 16; off > 0; off >>= 1) {
        float ov = __shfl_down_sync(0xffffffff, term, off);
        int   oi = __shfl_down_sync(0xffffffff, bi,   off);
        if (ov > term || (ov == term && oi < bi)) { term = ov; bi = oi; }
    }
    term = __shfl_sync(0xffffffff, term, 0);
    bi   = __shfl_sync(0xffffffff, bi,   0);

    if (lane == 0) {
        float* po = out;
        if (out_size > TT) { out[0] = term; po = out + 1; }
        int tag = bi;
        for (int t = TT - 1; t >= 0; t--) {
            po[t] = (float)tag;
            tag = bp[t * TAGS + tag];
        }
    }
}

// ---------------- launcher ----------------
extern "C" void kernel_launch(void* const* d_in, const int* in_sizes, int n_in,
                              void* d_out, int out_size)
{
    const float* features = (const float*)d_in[0];
    const float* conv1_w  = (const float*)d_in[1];
    const float* conv1_b  = (const float*)d_in[2];
    const float* conv3_w  = (const float*)d_in[3];
    const float* conv3_b  = (const float*)d_in[4];
    const float* conv5_w  = (const float*)d_in[5];
    const float* conv5_b  = (const float*)d_in[6];
    const float* wih0f = (const float*)d_in[7];
    const float* whh0f = (const float*)d_in[8];
    const float* bih0f = (const float*)d_in[9];
    const float* bhh0f = (const float*)d_in[10];
    const float* wih0r = (const float*)d_in[11];
    const float* whh0r = (const float*)d_in[12];
    const float* bih0r = (const float*)d_in[13];
    const float* bhh0r = (const float*)d_in[14];
    const float* wih1f = (const float*)d_in[15];
    const float* whh1f = (const float*)d_in[16];
    const float* bih1f = (const float*)d_in[17];
    const float* bhh1f = (const float*)d_in[18];
    const float* wih1r = (const float*)d_in[19];
    const float* whh1r = (const float*)d_in[20];
    const float* bih1r = (const float*)d_in[21];
    const float* bhh1r = (const float*)d_in[22];
    const float* h2t_w = (const float*)d_in[23];
    const float* h2t_b = (const float*)d_in[24];
    const float* trans = (const float*)d_in[25];

    float* out = (float*)d_out;

    float* px   = nullptr; cudaGetSymbolAddress((void**)&px,   d_x);
    float* pgxf = nullptr; cudaGetSymbolAddress((void**)&pgxf, d_gxf);
    float* pgxr = nullptr; cudaGetSymbolAddress((void**)&pgxr, d_gxr);
    float* py0  = nullptr; cudaGetSymbolAddress((void**)&py0,  d_y0);
    float* py1  = nullptr; cudaGetSymbolAddress((void**)&py1,  d_y1);
    float* plog = nullptr; cudaGetSymbolAddress((void**)&plog, d_logits);

    // 1. conv features
    conv_kernel<<<TT, 128>>>(features, conv1_w, conv1_b, conv3_w, conv3_b,
                             conv5_w, conv5_b, px);

    // 2. layer 0 input-gate GEMMs
    dim3 ggrid(GATES / 128, TT / 128);
    gemm128_kernel<<<ggrid, 256>>>(px, wih0f, bih0f, bhh0f, pgxf, TT, GATES, DIN);
    gemm128_kernel<<<ggrid, 256>>>(px, wih0r, bih0r, bhh0r, pgxr, TT, GATES, DIN);

    // 3. layer 0 recurrence
    zero_progress_kernel<<<1, 64>>>();
    recur_kernel<<<2 * RC_C, 256>>>(pgxf, pgxr, whh0f, whh0r, py0);

    // 4. layer 1 input-gate GEMMs
    gemm128_kernel<<<ggrid, 256>>>(py0, wih1f, bih1f, bhh1f, pgxf, TT, GATES, Y1DIM);
    gemm128_kernel<<<ggrid, 256>>>(py0, wih1r, bih1r, bhh1r, pgxr, TT, GATES, Y1DIM);

    // 5. layer 1 recurrence
    zero_progress_kernel<<<1, 64>>>();
    recur_kernel<<<2 * RC_C, 256>>>(pgxf, pgxr, whh1f, whh1r, py1);

    // 6. tag logits
    h2t_kernel<<<(TT * 32) / 256, 256>>>(py1, h2t_w, h2t_b, plog);

    // 7. Viterbi decode + output
    const int vit_smem = TT * TAGS + 32 * sizeof(float);
    cudaFuncSetAttribute(viterbi_kernel, cudaFuncAttributeMaxDynamicSharedMemorySize, vit_smem);
    viterbi_kernel<<<1, 32, vit_smem>>>(plog, trans, out, out_size);
}

// round 3
// speedup vs baseline: 1.2197x; 1.2197x over previous
#include <cuda_runtime.h>
#include <cuda_bf16.h>
#include <math.h>

// ---------------- problem constants ----------------
#define TT      8192          // sequence length
#define DIN     1728          // conv feature dim
#define HID     512
#define GATES   2048          // 4*HID
#define Y1DIM   1024          // 2*HID
#define TAGS    27
#define STARTT  25
#define STOPT   26

// recurrence partitioning
#define RC_C    32            // CTAs per direction
#define RC_U    16            // hidden units per CTA (512/32)

// ---------------- device scratch ----------------
__device__ float d_x   [TT * DIN];       // conv output features
__device__ float d_gxf [TT * GATES];     // precomputed input gates, fwd
__device__ float d_gxr [TT * GATES];     // precomputed input gates, bwd
__device__ float d_y0  [TT * Y1DIM];     // layer0 output (fwd | bwd)
__device__ float d_y1  [TT * Y1DIM];     // layer1 output
__device__ float d_logits[TT * 32];      // tag logits (stride 32, 27 used)

// mailbox: 16 h floats + step counter in one 128B line
struct __align__(128) Mail {
    float4   h[4];        // 64 B
    unsigned step;        // offset 64
    unsigned pad[15];
};
__device__ Mail d_mail[2][2][RC_C];      // [layer][dir][cta]

// ---------------- mailbox reset ----------------
__global__ void zero_mail_kernel()
{
    int i = threadIdx.x;                 // 128 = 2*2*32
    if (i < 2 * 2 * RC_C)
        ((Mail*)d_mail)[i].step = 0u;
}

// ---------------- conv feature kernel ----------------
__global__ void conv_kernel(const float* __restrict__ F,
                            const float* __restrict__ W1, const float* __restrict__ B1,
                            const float* __restrict__ W3, const float* __restrict__ B3,
                            const float* __restrict__ W5, const float* __restrict__ B5,
                            float* __restrict__ X)
{
    int t = blockIdx.x;
    __shared__ float fsh[448];
    __shared__ float w1s[448];
    __shared__ float w3s[768];
    __shared__ float w5s[1280];
    __shared__ float b1s[16], b3s[16], b5s[16];
    int tid = threadIdx.x;   // 128 threads

    for (int i = tid; i < 448;  i += 128) fsh[i] = F[t * 448 + i];
    for (int i = tid; i < 448;  i += 128) w1s[i] = W1[i];
    for (int i = tid; i < 768;  i += 128) w3s[i] = W3[i];
    for (int i = tid; i < 1280; i += 128) w5s[i] = W5[i];
    if (tid < 16) { b1s[tid] = B1[tid]; b3s[tid] = B3[tid]; b5s[tid] = B5[tid]; }
    __syncthreads();

    for (int idx = tid; idx < DIN; idx += 128) {
        float acc;
        if (idx < 192) {
            int c = idx / 12, w = idx % 12;
            acc = b1s[c];
            #pragma unroll
            for (int kh = 0; kh < 7; kh++)
                #pragma unroll
                for (int kw = 0; kw < 4; kw++)
                    acc = fmaf(fsh[kh * 64 + w * 4 + kw], w1s[c * 28 + kh * 4 + kw], acc);
        } else if (idx < 960) {
            int j = idx - 192;
            int c = j / 48, r = j % 48, h = r / 12, w = r % 12;
            acc = b3s[c];
            #pragma unroll
            for (int kh = 0; kh < 4; kh++)
                #pragma unroll
                for (int kw = 0; kw < 12; kw++)
                    acc = fmaf(fsh[(h + kh) * 64 + w * 4 + kw], w3s[c * 48 + kh * 12 + kw], acc);
        } else {
            int j = idx - 960;
            int c = j / 48, r = j % 48, h = r / 12, w = r % 12;
            acc = b5s[c];
            #pragma unroll
            for (int kh = 0; kh < 4; kh++)
                #pragma unroll
                for (int kw = 0; kw < 20; kw++)
                    acc = fmaf(fsh[(h + kh) * 64 + w * 4 + kw], w5s[c * 80 + kh * 20 + kw], acc);
        }
        X[(size_t)t * DIN + idx] = acc;
    }
}

// ---------------- fp32 tiled GEMM (double-buffered), dual weight sets ----------------
// C[M,N] = A[M,K] @ B[N,K]^T + b1[n] + b2[n]; blockIdx.z selects (B, b1, b2, C)
__global__ __launch_bounds__(256) void gemm_dual_kernel(
    const float* __restrict__ A,
    const float* __restrict__ B0, const float* __restrict__ b0a,
    const float* __restrict__ b0b, float* __restrict__ C0,
    const float* __restrict__ B1, const float* __restrict__ b1a,
    const float* __restrict__ b1b, float* __restrict__ C1,
    int M, int N, int K)
{
    const float* B     = blockIdx.z ? B1  : B0;
    const float* bias1 = blockIdx.z ? b1a : b0a;
    const float* bias2 = blockIdx.z ? b1b : b0b;
    float*       C     = blockIdx.z ? C1  : C0;

    __shared__ float As[2][16][128];
    __shared__ float Bs[2][16][128];
    const int tid = threadIdx.x;
    const int m0 = blockIdx.y * 128;
    const int n0 = blockIdx.x * 128;
    const int tx = tid & 15;
    const int ty = tid >> 4;

    // load geometry: two row-slices per thread per matrix
    const int row0 = tid >> 2;            // 0..63
    const int row1 = row0 + 64;           // 64..127
    const int kq4  = (tid & 3) * 4;

    const float* Ap0 = A + (size_t)(m0 + row0) * K + kq4;
    const float* Ap1 = A + (size_t)(m0 + row1) * K + kq4;
    const float* Bp0 = B + (size_t)(n0 + row0) * K + kq4;
    const float* Bp1 = B + (size_t)(n0 + row1) * K + kq4;

    float acc[8][8];
    #pragma unroll
    for (int i = 0; i < 8; i++)
        #pragma unroll
        for (int j = 0; j < 8; j++) acc[i][j] = 0.f;

    float4 pa0 = *(const float4*)(Ap0);
    float4 pa1 = *(const float4*)(Ap1);
    float4 pb0 = *(const float4*)(Bp0);
    float4 pb1 = *(const float4*)(Bp1);

    // store first tile into buffer 0
    As[0][kq4 + 0][row0] = pa0.x; As[0][kq4 + 1][row0] = pa0.y;
    As[0][kq4 + 2][row0] = pa0.z; As[0][kq4 + 3][row0] = pa0.w;
    As[0][kq4 + 0][row1] = pa1.x; As[0][kq4 + 1][row1] = pa1.y;
    As[0][kq4 + 2][row1] = pa1.z; As[0][kq4 + 3][row1] = pa1.w;
    Bs[0][kq4 + 0][row0] = pb0.x; Bs[0][kq4 + 1][row0] = pb0.y;
    Bs[0][kq4 + 2][row0] = pb0.z; Bs[0][kq4 + 3][row0] = pb0.w;
    Bs[0][kq4 + 0][row1] = pb1.x; Bs[0][kq4 + 1][row1] = pb1.y;
    Bs[0][kq4 + 2][row1] = pb1.z; Bs[0][kq4 + 3][row1] = pb1.w;
    __syncthreads();

    int buf = 0;
    for (int k0 = 0; k0 < K; k0 += 16) {
        const bool more = (k0 + 16) < K;
        if (more) {
            pa0 = *(const float4*)(Ap0 + k0 + 16);
            pa1 = *(const float4*)(Ap1 + k0 + 16);
            pb0 = *(const float4*)(Bp0 + k0 + 16);
            pb1 = *(const float4*)(Bp1 + k0 + 16);
        }

        #pragma unroll
        for (int k = 0; k < 16; k++) {
            float a[8], b[8];
            #pragma unroll
            for (int i = 0; i < 8; i++) a[i] = As[buf][k][ty * 8 + i];
            #pragma unroll
            for (int j = 0; j < 8; j++) b[j] = Bs[buf][k][tx * 8 + j];
            #pragma unroll
            for (int i = 0; i < 8; i++)
                #pragma unroll
                for (int j = 0; j < 8; j++)
                    acc[i][j] = fmaf(a[i], b[j], acc[i][j]);
        }

        if (more) {
            int nb = buf ^ 1;
            As[nb][kq4 + 0][row0] = pa0.x; As[nb][kq4 + 1][row0] = pa0.y;
            As[nb][kq4 + 2][row0] = pa0.z; As[nb][kq4 + 3][row0] = pa0.w;
            As[nb][kq4 + 0][row1] = pa1.x; As[nb][kq4 + 1][row1] = pa1.y;
            As[nb][kq4 + 2][row1] = pa1.z; As[nb][kq4 + 3][row1] = pa1.w;
            Bs[nb][kq4 + 0][row0] = pb0.x; Bs[nb][kq4 + 1][row0] = pb0.y;
            Bs[nb][kq4 + 2][row0] = pb0.z; Bs[nb][kq4 + 3][row0] = pb0.w;
            Bs[nb][kq4 + 0][row1] = pb1.x; Bs[nb][kq4 + 1][row1] = pb1.y;
            Bs[nb][kq4 + 2][row1] = pb1.z; Bs[nb][kq4 + 3][row1] = pb1.w;
            __syncthreads();
            buf = nb;
        }
    }

    #pragma unroll
    for (int i = 0; i < 8; i++) {
        int m = m0 + ty * 8 + i;
        #pragma unroll
        for (int j = 0; j < 8; j++) {
            int n = n0 + tx * 8 + j;
            C[(size_t)m * N + n] = acc[i][j] + bias1[n] + bias2[n];
        }
    }
}

// ---------------- persistent bidirectional LSTM recurrence ----------------
// grid = 64 CTAs: blocks [0,32) forward, [32,64) backward, 256 threads each.
// Each CTA owns RC_U hidden units; its 64 x 512 Whh slice is held in registers.
// h exchange through 128B mailbox lines with release/acquire publication.
__device__ __forceinline__ float sigm(float x) { return 1.f / (1.f + expf(-x)); }

__global__ __launch_bounds__(256, 1) void recur_kernel(
    const float* __restrict__ gx_f, const float* __restrict__ gx_r,
    const float* __restrict__ whh_f, const float* __restrict__ whh_r,
    float* __restrict__ y, int layer)
{
    const int dir = blockIdx.x >> 5;          // 0 fwd, 1 bwd
    const int cta = blockIdx.x & 31;
    const float* __restrict__ gx  = dir ? gx_r  : gx_f;
    const float* __restrict__ whh = dir ? whh_r : whh_f;
    Mail* mail = d_mail[layer][dir];

    const int u0  = cta * RC_U;
    const int tid = threadIdx.x;
    const int warp = tid >> 5, lane = tid & 31;
    const int kq = warp & 3;                  // k-quarter (128 k each)
    const int rg = warp >> 2;                 // row group (32 rows each)
    const int lr = rg * 32 + lane;            // local gate row 0..63
    const int gate = lr >> 4, uu = lr & 15;
    const int grow = gate * 512 + u0 + uu;    // global gate row in Whh / gx
    const int kbase = kq * 128;

    __shared__ float hsh[512];
    __shared__ float red[4][64];
    __shared__ float gsh[64];
    __shared__ float hloc[16];

    // one-time: Whh slice into registers (128 floats / thread)
    float w[128];
    {
        const float4* wp = (const float4*)(whh + (size_t)grow * 512 + kbase);
        #pragma unroll
        for (int j = 0; j < 32; j++) {
            float4 v = wp[j];
            w[4 * j + 0] = v.x; w[4 * j + 1] = v.y;
            w[4 * j + 2] = v.z; w[4 * j + 3] = v.w;
        }
    }

    float c_state = 0.f;   // live in threads 0..15
    const int gxi = (tid >> 4) * 512 + u0 + (tid & 15);   // gate row for gx fetch (tid<64)

    for (int s = 0; s < TT; s++) {
        const int tt = dir ? (TT - 1 - s) : s;

        // prefetch this step's gx contribution (independent of h)
        float gxv = 0.f;
        if (tid < 64) gxv = gx[(size_t)tt * GATES + gxi];

        if (s > 0) {
            // wait for all producer mailboxes of this direction at step >= s,
            // then pull h straight out of the mailbox line (hot in L2)
            if (tid < RC_C) {
                const unsigned* fp = &mail[tid].step;
                unsigned v;
                do {
                    asm volatile("ld.global.acquire.gpu.u32 %0, [%1];"
                                 : "=r"(v) : "l"(fp) : "memory");
                } while (v < (unsigned)s);
                const float4* hp4 = mail[tid].h;
                float4 a0 = hp4[0], a1 = hp4[1], a2 = hp4[2], a3 = hp4[3];
                float4* dst = ((float4*)hsh) + tid * 4;
                dst[0] = a0; dst[1] = a1; dst[2] = a2; dst[3] = a3;
            }
            __syncthreads();

            // matvec: each thread 128 MACs over its register-resident weights
            float a0 = 0.f, a1 = 0.f, a2 = 0.f, a3 = 0.f;
            #pragma unroll
            for (int j = 0; j < 32; j++) {
                float4 hv = *(const float4*)&hsh[kbase + 4 * j];
                a0 = fmaf(w[4 * j + 0], hv.x, a0);
                a1 = fmaf(w[4 * j + 1], hv.y, a1);
                a2 = fmaf(w[4 * j + 2], hv.z, a2);
                a3 = fmaf(w[4 * j + 3], hv.w, a3);
            }
            red[kq][lr] = (a0 + a1) + (a2 + a3);
            __syncthreads();

            if (tid < 64)
                gsh[tid] = red[0][tid] + red[1][tid] + red[2][tid] + red[3][tid] + gxv;
        } else {
            if (tid < 64) gsh[tid] = gxv;
        }
        __syncthreads();

        // gate nonlinearities + state update (threads 0..15 own the units)
        if (tid < 16) {
            float gi = gsh[tid];
            float gf = gsh[16 + tid];
            float gg = gsh[32 + tid];
            float go = gsh[48 + tid];
            c_state = sigm(gf) * c_state + sigm(gi) * tanhf(gg);
            float h = sigm(go) * tanhf(c_state);
            hloc[tid] = h;
            y[(size_t)tt * Y1DIM + dir * HID + u0 + tid] = h;   // layer output (off critical path)
        }
        __syncwarp();          // warp 0 only reaches here together
        if (tid == 0) {
            float4 h0 = ((const float4*)hloc)[0];
            float4 h1 = ((const float4*)hloc)[1];
            float4 h2 = ((const float4*)hloc)[2];
            float4 h3 = ((const float4*)hloc)[3];
            float4* mb = mail[cta].h;
            mb[0] = h0; mb[1] = h1; mb[2] = h2; mb[3] = h3;
            asm volatile("st.global.release.gpu.u32 [%0], %1;"
                         :: "l"(&mail[cta].step), "r"((unsigned)(s + 1)) : "memory");
        }
        // no trailing barrier needed: next iteration's post-poll __syncthreads
        // orders every cross-warp shared-memory reuse (see hazard analysis)
    }
}

// ---------------- tag head: logits = y1 @ h2t_w^T + b ----------------
__global__ void h2t_kernel(const float* __restrict__ Y, const float* __restrict__ W,
                           const float* __restrict__ B, float* __restrict__ L)
{
    int id = blockIdx.x * blockDim.x + threadIdx.x;
    int t = id >> 5;
    int n = id & 31;
    if (t >= TT || n >= TAGS) return;
    const float4* yr = (const float4*)(Y + (size_t)t * Y1DIM);
    const float4* wr = (const float4*)(W + (size_t)n * Y1DIM);
    float acc = 0.f;
    #pragma unroll 8
    for (int k = 0; k < Y1DIM / 4; k++) {
        float4 a = yr[k], b = wr[k];
        acc = fmaf(a.x, b.x, acc);
        acc = fmaf(a.y, b.y, acc);
        acc = fmaf(a.z, b.z, acc);
        acc = fmaf(a.w, b.w, acc);
    }
    L[t * 32 + n] = acc + B[n];
}

// ---------------- Viterbi (single warp, backpointers in SMEM) ----------------
__global__ void viterbi_kernel(const float* __restrict__ L, const float* __restrict__ trans,
                               float* __restrict__ out, int out_size)
{
    extern __shared__ unsigned char sm[];
    unsigned char* bp = sm;                              // TT * TAGS bytes
    float* fvs = (float*)(sm + TT * TAGS);               // 27 floats (221184 % 4 == 0)
    const int lane = threadIdx.x;

    float tr[TAGS];
    if (lane < TAGS) {
        #pragma unroll
        for (int p = 0; p < TAGS; p++) tr[p] = trans[lane * TAGS + p];
        fvs[lane] = (lane == STARTT) ? 0.f : -10000.f;
    }
    __syncwarp();

    float feat = (lane < TAGS) ? L[lane] : 0.f;          // prefetch t=0
    for (int t = 0; t < TT; t++) {
        float nfeat = 0.f;
        if (t + 1 < TT && lane < TAGS) nfeat = L[(t + 1) * 32 + lane];  // prefetch t+1

        float sc[TAGS];
        float best = -3.4e38f;
        int arg = 0;
        if (lane < TAGS) {
            #pragma unroll
            for (int p = 0; p < TAGS; p++) sc[p] = fvs[p] + tr[p];
            best = sc[0];
            #pragma unroll
            for (int p = 1; p < TAGS; p++) best = fmaxf(best, sc[p]);
            arg = TAGS - 1;
            #pragma unroll
            for (int p = TAGS - 2; p >= 0; p--) if (sc[p] == best) arg = p;  // first max
        }
        __syncwarp();
        if (lane < TAGS) {
            fvs[lane] = best + feat;
            bp[t * TAGS + lane] = (unsigned char)arg;
        }
        __syncwarp();
        feat = nfeat;
    }

    float term = (lane < TAGS) ? fvs[lane] + trans[STOPT * TAGS + lane] : -3.4e38f;
    int bi = lane;
    #pragma unroll
    for (int off = 16; off > 0; off >>= 1) {
        float ov = __shfl_down_sync(0xffffffff, term, off);
        int   oi = __shfl_down_sync(0xffffffff, bi,   off);
        if (ov > term || (ov == term && oi < bi)) { term = ov; bi = oi; }
    }
    term = __shfl_sync(0xffffffff, term, 0);
    bi   = __shfl_sync(0xffffffff, bi,   0);

    if (lane == 0) {
        float* po = out;
        if (out_size > TT) { out[0] = term; po = out + 1; }
        int tag = bi;
        for (int t = TT - 1; t >= 0; t--) {
            po[t] = (float)tag;
            tag = bp[t * TAGS + tag];
        }
    }
}

// ---------------- launcher ----------------
extern "C" void kernel_launch(void* const* d_in, const int* in_sizes, int n_in,
                              void* d_out, int out_size)
{
    const float* features = (const float*)d_in[0];
    const float* conv1_w  = (const float*)d_in[1];
    const float* conv1_b  = (const float*)d_in[2];
    const float* conv3_w  = (const float*)d_in[3];
    const float* conv3_b  = (const float*)d_in[4];
    const float* conv5_w  = (const float*)d_in[5];
    const float* conv5_b  = (const float*)d_in[6];
    const float* wih0f = (const float*)d_in[7];
    const float* whh0f = (const float*)d_in[8];
    const float* bih0f = (const float*)d_in[9];
    const float* bhh0f = (const float*)d_in[10];
    const float* wih0r = (const float*)d_in[11];
    const float* whh0r = (const float*)d_in[12];
    const float* bih0r = (const float*)d_in[13];
    const float* bhh0r = (const float*)d_in[14];
    const float* wih1f = (const float*)d_in[15];
    const float* whh1f = (const float*)d_in[16];
    const float* bih1f = (const float*)d_in[17];
    const float* bhh1f = (const float*)d_in[18];
    const float* wih1r = (const float*)d_in[19];
    const float* whh1r = (const float*)d_in[20];
    const float* bih1r = (const float*)d_in[21];
    const float* bhh1r = (const float*)d_in[22];
    const float* h2t_w = (const float*)d_in[23];
    const float* h2t_b = (const float*)d_in[24];
    const float* trans = (const float*)d_in[25];

    float* out = (float*)d_out;

    float* px   = nullptr; cudaGetSymbolAddress((void**)&px,   d_x);
    float* pgxf = nullptr; cudaGetSymbolAddress((void**)&pgxf, d_gxf);
    float* pgxr = nullptr; cudaGetSymbolAddress((void**)&pgxr, d_gxr);
    float* py0  = nullptr; cudaGetSymbolAddress((void**)&py0,  d_y0);
    float* py1  = nullptr; cudaGetSymbolAddress((void**)&py1,  d_y1);
    float* plog = nullptr; cudaGetSymbolAddress((void**)&plog, d_logits);

    // 1. reset mailboxes (both layers)
    zero_mail_kernel<<<1, 128>>>();

    // 2. conv features
    conv_kernel<<<TT, 128>>>(features, conv1_w, conv1_b, conv3_w, conv3_b,
                             conv5_w, conv5_b, px);

    // 3. layer 0 input-gate GEMMs (fwd + bwd in one launch)
    dim3 ggrid(GATES / 128, TT / 128, 2);
    gemm_dual_kernel<<<ggrid, 256>>>(px,
                                     wih0f, bih0f, bhh0f, pgxf,
                                     wih0r, bih0r, bhh0r, pgxr,
                                     TT, GATES, DIN);

    // 4. layer 0 recurrence
    recur_kernel<<<2 * RC_C, 256>>>(pgxf, pgxr, whh0f, whh0r, py0, 0);

    // 5. layer 1 input-gate GEMMs
    gemm_dual_kernel<<<ggrid, 256>>>(py0,
                                     wih1f, bih1f, bhh1f, pgxf,
                                     wih1r, bih1r, bhh1r, pgxr,
                                     TT, GATES, Y1DIM);

    // 6. layer 1 recurrence
    recur_kernel<<<2 * RC_C, 256>>>(pgxf, pgxr, whh1f, whh1r, py1, 1);

    // 7. tag logits
    h2t_kernel<<<(TT * 32) / 256, 256>>>(py1, h2t_w, h2t_b, plog);

    // 8. Viterbi decode + output
    const int vit_smem = TT * TAGS + 32 * sizeof(float);
    cudaFuncSetAttribute(viterbi_kernel, cudaFuncAttributeMaxDynamicSharedMemorySize, vit_smem);
    viterbi_kernel<<<1, 32, vit_smem>>>(plog, trans, out, out_size);
}

// round 4
// speedup vs baseline: 1.9631x; 1.6095x over previous
#include <cuda_runtime.h>
#include <cuda_bf16.h>
#include <math.h>

// ---------------- problem constants ----------------
#define TT      8192
#define DIN     1728
#define HID     512
#define GATES   2048
#define Y1DIM   1024
#define TAGS    27
#define STARTT  25
#define STOPT   26

// recurrence partitioning: 64 CTAs per direction, 8 hidden units per CTA
#define RC_C    64
#define RC_U    8

// ---------------- device scratch ----------------
__device__ float d_x   [TT * DIN];
__device__ float d_gxf [TT * GATES];
__device__ float d_gxr [TT * GATES];
__device__ float d_y0  [TT * Y1DIM];
__device__ float d_y1  [TT * Y1DIM];
__device__ float d_logits[TT * 32];

// self-validating mailboxes: [layer][dir][slot][cta*8+unit]
// each float carries (step & 3) in its 2 LSBs; slot = step & 1
__device__ float d_mail[2][2][2][RC_C * RC_U];

// ---------------- f32x2 helpers ----------------
__device__ __forceinline__ void ffma2(unsigned long long& d,
                                      unsigned long long a, unsigned long long b) {
    asm("fma.rn.f32x2 %0, %1, %2, %0;" : "+l"(d) : "l"(a), "l"(b));
}
__device__ __forceinline__ unsigned long long pack2(float x, float y) {
    unsigned long long r;
    asm("mov.b64 %0, {%1, %2};" : "=l"(r) : "f"(x), "f"(y));
    return r;
}
__device__ __forceinline__ float2 unpack2(unsigned long long v) {
    float2 r;
    asm("mov.b64 {%0, %1}, %2;" : "=f"(r.x), "=f"(r.y) : "l"(v));
    return r;
}

// fast gates (MUFU-based, clamp-safe)
__device__ __forceinline__ float sigm_f(float x) {
    return __fdividef(1.f, 1.f + __expf(-x));
}
__device__ __forceinline__ float tanh_f(float x) {
    float e = __expf(-2.f * fabsf(x));          // e in (0,1] -> no inf/NaN
    float r = __fdividef(1.f - e, 1.f + e);
    return copysignf(r, x);
}

// ---------------- mailbox poison ----------------
// slot0 holds even-step tags {0,2}: poison with tag 1.
// slot1 holds odd-step tags {1,3}: poison with tag 0.
__global__ void zero_mail_kernel()
{
    float* base = &d_mail[0][0][0][0];
    const int total = 2 * 2 * 2 * RC_C * RC_U;          // 4096
    for (int i = threadIdx.x; i < total; i += blockDim.x) {
        int slot = (i >> 9) & 1;
        unsigned bits = slot ? 0u : 1u;
        base[i] = __uint_as_float(bits);
    }
}

// ---------------- conv feature kernel ----------------
__global__ void conv_kernel(const float* __restrict__ F,
                            const float* __restrict__ W1, const float* __restrict__ B1,
                            const float* __restrict__ W3, const float* __restrict__ B3,
                            const float* __restrict__ W5, const float* __restrict__ B5,
                            float* __restrict__ X)
{
    int t = blockIdx.x;
    __shared__ float fsh[448];
    __shared__ float w1s[448];
    __shared__ float w3s[768];
    __shared__ float w5s[1280];
    __shared__ float b1s[16], b3s[16], b5s[16];
    int tid = threadIdx.x;   // 128 threads

    for (int i = tid; i < 448;  i += 128) fsh[i] = F[t * 448 + i];
    for (int i = tid; i < 448;  i += 128) w1s[i] = W1[i];
    for (int i = tid; i < 768;  i += 128) w3s[i] = W3[i];
    for (int i = tid; i < 1280; i += 128) w5s[i] = W5[i];
    if (tid < 16) { b1s[tid] = B1[tid]; b3s[tid] = B3[tid]; b5s[tid] = B5[tid]; }
    __syncthreads();

    for (int idx = tid; idx < DIN; idx += 128) {
        float acc;
        if (idx < 192) {
            int c = idx / 12, w = idx % 12;
            acc = b1s[c];
            #pragma unroll
            for (int kh = 0; kh < 7; kh++)
                #pragma unroll
                for (int kw = 0; kw < 4; kw++)
                    acc = fmaf(fsh[kh * 64 + w * 4 + kw], w1s[c * 28 + kh * 4 + kw], acc);
        } else if (idx < 960) {
            int j = idx - 192;
            int c = j / 48, r = j % 48, h = r / 12, w = r % 12;
            acc = b3s[c];
            #pragma unroll
            for (int kh = 0; kh < 4; kh++)
                #pragma unroll
                for (int kw = 0; kw < 12; kw++)
                    acc = fmaf(fsh[(h + kh) * 64 + w * 4 + kw], w3s[c * 48 + kh * 12 + kw], acc);
        } else {
            int j = idx - 960;
            int c = j / 48, r = j % 48, h = r / 12, w = r % 12;
            acc = b5s[c];
            #pragma unroll
            for (int kh = 0; kh < 4; kh++)
                #pragma unroll
                for (int kw = 0; kw < 20; kw++)
                    acc = fmaf(fsh[(h + kh) * 64 + w * 4 + kw], w5s[c * 80 + kh * 20 + kw], acc);
        }
        X[(size_t)t * DIN + idx] = acc;
    }
}

// ---------------- fp32 tiled GEMM (double-buffered, f32x2 compute), dual weight sets ----
__global__ __launch_bounds__(256) void gemm_dual_kernel(
    const float* __restrict__ A,
    const float* __restrict__ B0, const float* __restrict__ b0a,
    const float* __restrict__ b0b, float* __restrict__ C0,
    const float* __restrict__ B1, const float* __restrict__ b1a,
    const float* __restrict__ b1b, float* __restrict__ C1,
    int M, int N, int K)
{
    const float* B     = blockIdx.z ? B1  : B0;
    const float* bias1 = blockIdx.z ? b1a : b0a;
    const float* bias2 = blockIdx.z ? b1b : b0b;
    float*       C     = blockIdx.z ? C1  : C0;

    __shared__ __align__(16) float As[2][16][128];
    __shared__ __align__(16) float Bs[2][16][128];
    const int tid = threadIdx.x;
    const int m0 = blockIdx.y * 128;
    const int n0 = blockIdx.x * 128;
    const int tx = tid & 15;
    const int ty = tid >> 4;

    const int row0 = tid >> 2;
    const int row1 = row0 + 64;
    const int kq4  = (tid & 3) * 4;

    const float* Ap0 = A + (size_t)(m0 + row0) * K + kq4;
    const float* Ap1 = A + (size_t)(m0 + row1) * K + kq4;
    const float* Bp0 = B + (size_t)(n0 + row0) * K + kq4;
    const float* Bp1 = B + (size_t)(n0 + row1) * K + kq4;

    unsigned long long acc2[8][4];
    #pragma unroll
    for (int i = 0; i < 8; i++)
        #pragma unroll
        for (int j = 0; j < 4; j++) acc2[i][j] = 0ull;

    float4 pa0 = *(const float4*)(Ap0);
    float4 pa1 = *(const float4*)(Ap1);
    float4 pb0 = *(const float4*)(Bp0);
    float4 pb1 = *(const float4*)(Bp1);

    As[0][kq4 + 0][row0] = pa0.x; As[0][kq4 + 1][row0] = pa0.y;
    As[0][kq4 + 2][row0] = pa0.z; As[0][kq4 + 3][row0] = pa0.w;
    As[0][kq4 + 0][row1] = pa1.x; As[0][kq4 + 1][row1] = pa1.y;
    As[0][kq4 + 2][row1] = pa1.z; As[0][kq4 + 3][row1] = pa1.w;
    Bs[0][kq4 + 0][row0] = pb0.x; Bs[0][kq4 + 1][row0] = pb0.y;
    Bs[0][kq4 + 2][row0] = pb0.z; Bs[0][kq4 + 3][row0] = pb0.w;
    Bs[0][kq4 + 0][row1] = pb1.x; Bs[0][kq4 + 1][row1] = pb1.y;
    Bs[0][kq4 + 2][row1] = pb1.z; Bs[0][kq4 + 3][row1] = pb1.w;
    __syncthreads();

    int buf = 0;
    for (int k0 = 0; k0 < K; k0 += 16) {
        const bool more = (k0 + 16) < K;
        if (more) {
            pa0 = *(const float4*)(Ap0 + k0 + 16);
            pa1 = *(const float4*)(Ap1 + k0 + 16);
            pb0 = *(const float4*)(Bp0 + k0 + 16);
            pb1 = *(const float4*)(Bp1 + k0 + 16);
        }

        #pragma unroll
        for (int k = 0; k < 16; k++) {
            float4 a0 = *(const float4*)&As[buf][k][ty * 8];
            float4 a1 = *(const float4*)&As[buf][k][ty * 8 + 4];
            unsigned long long b2[4];
            {
                const ulonglong2* bp = (const ulonglong2*)&Bs[buf][k][tx * 8];
                ulonglong2 v0 = bp[0], v1 = bp[1];
                b2[0] = v0.x; b2[1] = v0.y; b2[2] = v1.x; b2[3] = v1.y;
            }
            float av[8] = {a0.x, a0.y, a0.z, a0.w, a1.x, a1.y, a1.z, a1.w};
            #pragma unroll
            for (int i = 0; i < 8; i++) {
                unsigned long long ai = pack2(av[i], av[i]);
                #pragma unroll
                for (int jp = 0; jp < 4; jp++)
                    ffma2(acc2[i][jp], ai, b2[jp]);
            }
        }

        if (more) {
            int nb = buf ^ 1;
            As[nb][kq4 + 0][row0] = pa0.x; As[nb][kq4 + 1][row0] = pa0.y;
            As[nb][kq4 + 2][row0] = pa0.z; As[nb][kq4 + 3][row0] = pa0.w;
            As[nb][kq4 + 0][row1] = pa1.x; As[nb][kq4 + 1][row1] = pa1.y;
            As[nb][kq4 + 2][row1] = pa1.z; As[nb][kq4 + 3][row1] = pa1.w;
            Bs[nb][kq4 + 0][row0] = pb0.x; Bs[nb][kq4 + 1][row0] = pb0.y;
            Bs[nb][kq4 + 2][row0] = pb0.z; Bs[nb][kq4 + 3][row0] = pb0.w;
            Bs[nb][kq4 + 0][row1] = pb1.x; Bs[nb][kq4 + 1][row1] = pb1.y;
            Bs[nb][kq4 + 2][row1] = pb1.z; Bs[nb][kq4 + 3][row1] = pb1.w;
            __syncthreads();
            buf = nb;
        }
    }

    #pragma unroll
    for (int i = 0; i < 8; i++) {
        int m = m0 + ty * 8 + i;
        float* Crow = C + (size_t)m * N + n0 + tx * 8;
        #pragma unroll
        for (int jp = 0; jp < 4; jp++) {
            float2 v = unpack2(acc2[i][jp]);
            int n = n0 + tx * 8 + 2 * jp;
            Crow[2 * jp + 0] = v.x + bias1[n + 0] + bias2[n + 0];
            Crow[2 * jp + 1] = v.y + bias1[n + 1] + bias2[n + 1];
        }
    }
}

// ---------------- persistent bidirectional LSTM recurrence ----------------
// grid = 128 CTAs: [0,64) forward, [64,128) backward; 256 threads each.
// CTA owns 8 hidden units (32 gate rows); weights in registers (64 floats/thread).
// h exchange: self-tagged double-buffered mailboxes, single L2 hop.
__global__ __launch_bounds__(256, 1) void recur_kernel(
    const float* __restrict__ gx_f, const float* __restrict__ gx_r,
    const float* __restrict__ whh_f, const float* __restrict__ whh_r,
    float* __restrict__ y, int layer)
{
    const int dir = blockIdx.x >> 6;
    const int cta = blockIdx.x & 63;
    const float* __restrict__ gx  = dir ? gx_r  : gx_f;
    const float* __restrict__ whh = dir ? whh_r : whh_f;
    float* slotA = &d_mail[layer][dir][0][0];
    float* slotB = &d_mail[layer][dir][1][0];

    const int u0   = cta * RC_U;
    const int tid  = threadIdx.x;
    const int warp = tid >> 5, lane = tid & 31;

    // matvec mapping: r = lane (gate row 0..31), ks = warp (k-slice of 64)
    const int r    = lane;
    const int ks   = warp;
    const int gate = r >> 3, uu = r & 7;
    const int grow = gate * 512 + u0 + uu;     // global gate row

    __shared__ __align__(16) float hsh[512];
    __shared__ float red[8][32];

    // weights: 64 floats/thread as 32 packed f32x2
    unsigned long long w2[32];
    {
        const ulonglong2* wp = (const ulonglong2*)(whh + (size_t)grow * 512 + ks * 64);
        #pragma unroll
        for (int j = 0; j < 16; j++) {
            ulonglong2 v = wp[j];
            w2[2 * j] = v.x; w2[2 * j + 1] = v.y;
        }
    }

    float c_state = 0.f;   // lives in warp 0 lanes 0..7

    for (int s = 0; s < TT; s++) {
        const int tt = dir ? (TT - 1 - s) : s;

        // prefetch gx (warp 0 only needs it) — independent of h, overlaps polling
        float gxv = 0.f;
        if (warp == 0) gxv = gx[(size_t)tt * GATES + grow];

        if (s > 0) {
            // poll peer granules: tid<128, one 16B granule each (4 self-tagged floats)
            if (tid < 128) {
                const float* src = (((s - 1) & 1) ? slotB : slotA) + (tid << 2);
                const unsigned want = (unsigned)((s - 1) & 3);
                float4 v;
                unsigned bad;
                do {
                    asm volatile("ld.volatile.global.v4.f32 {%0,%1,%2,%3}, [%4];"
                                 : "=f"(v.x), "=f"(v.y), "=f"(v.z), "=f"(v.w)
                                 : "l"(src));
                    bad  = (__float_as_uint(v.x) & 3u) ^ want;
                    bad |= (__float_as_uint(v.y) & 3u) ^ want;
                    bad |= (__float_as_uint(v.z) & 3u) ^ want;
                    bad |= (__float_as_uint(v.w) & 3u) ^ want;
                } while (bad);
                *(float4*)&hsh[tid << 2] = v;
            }
        }
        __syncthreads();   // barrier A

        if (s > 0) {
            // matvec over this thread's 64-wide k-slice, packed f32x2, 2 acc chains
            const ulonglong2* hp = (const ulonglong2*)(hsh + ks * 64);
            unsigned long long accA = 0ull, accB = 0ull;
            #pragma unroll
            for (int j = 0; j < 16; j++) {
                ulonglong2 hv = hp[j];
                ffma2(accA, w2[2 * j],     hv.x);
                ffma2(accB, w2[2 * j + 1], hv.y);
            }
            float2 fa = unpack2(accA), fb = unpack2(accB);
            red[ks][r] = (fa.x + fa.y) + (fb.x + fb.y);
        }
        __syncthreads();   // barrier B

        if (warp == 0) {
            float sum = gxv;
            if (s > 0) {
                float s0 = red[0][lane] + red[1][lane];
                float s1 = red[2][lane] + red[3][lane];
                float s2 = red[4][lane] + red[5][lane];
                float s3 = red[6][lane] + red[7][lane];
                sum += (s0 + s1) + (s2 + s3);
            }
            // per-gate nonlinearity in parallel across lanes
            float nl = (gate == 2) ? tanh_f(sum) : sigm_f(sum);
            // lanes 0..7 gather the 4 gate values of their unit
            float sf = __shfl_sync(0xffffffffu, nl, lane + 8);
            float tg = __shfl_sync(0xffffffffu, nl, lane + 16);
            float so = __shfl_sync(0xffffffffu, nl, lane + 24);
            if (lane < 8) {
                c_state = sf * c_state + nl * tg;         // nl = sigm(i) for lanes 0..7
                float h = so * tanh_f(c_state);
                unsigned hb = (__float_as_uint(h) & ~3u) | (unsigned)(s & 3);
                float he = __uint_as_float(hb);
                float* dst = ((s & 1) ? slotB : slotA) + u0 + lane;
                asm volatile("st.volatile.global.f32 [%0], %1;" :: "l"(dst), "f"(he));
                y[(size_t)tt * Y1DIM + dir * HID + u0 + lane] = he;
            }
        }
        // overwrite hazards for hsh/red are gated by the mailbox protocol itself
    }
}

// ---------------- tag head: logits = y1 @ h2t_w^T + b ----------------
__global__ void h2t_kernel(const float* __restrict__ Y, const float* __restrict__ W,
                           const float* __restrict__ B, float* __restrict__ L)
{
    int id = blockIdx.x * blockDim.x + threadIdx.x;
    int t = id >> 5;
    int n = id & 31;
    if (t >= TT || n >= TAGS) return;
    const float4* yr = (const float4*)(Y + (size_t)t * Y1DIM);
    const float4* wr = (const float4*)(W + (size_t)n * Y1DIM);
    float acc = 0.f;
    #pragma unroll 8
    for (int k = 0; k < Y1DIM / 4; k++) {
        float4 a = yr[k], b = wr[k];
        acc = fmaf(a.x, b.x, acc);
        acc = fmaf(a.y, b.y, acc);
        acc = fmaf(a.z, b.z, acc);
        acc = fmaf(a.w, b.w, acc);
    }
    L[t * 32 + n] = acc + B[n];
}

// ---------------- Viterbi (single warp, backpointers in SMEM) ----------------
__global__ void viterbi_kernel(const float* __restrict__ L, const float* __restrict__ trans,
                               float* __restrict__ out, int out_size)
{
    extern __shared__ unsigned char sm[];
    unsigned char* bp = sm;                              // TT * TAGS bytes
    float* fvs = (float*)(sm + TT * TAGS);
    const int lane = threadIdx.x;

    float tr[TAGS];
    if (lane < TAGS) {
        #pragma unroll
        for (int p = 0; p < TAGS; p++) tr[p] = trans[lane * TAGS + p];
        fvs[lane] = (lane == STARTT) ? 0.f : -10000.f;
    }
    __syncwarp();

    float feat = (lane < TAGS) ? L[lane] : 0.f;
    for (int t = 0; t < TT; t++) {
        float nfeat = 0.f;
        if (t + 1 < TT && lane < TAGS) nfeat = L[(t + 1) * 32 + lane];

        float best = 0.f;
        int arg = 0;
        if (lane < TAGS) {
            float sc[TAGS];
            float v[32];
            #pragma unroll
            for (int p = 0; p < TAGS; p++) { sc[p] = fvs[p] + tr[p]; v[p] = sc[p]; }
            #pragma unroll
            for (int p = TAGS; p < 32; p++) v[p] = -3.4e38f;
            #pragma unroll
            for (int st = 16; st >= 1; st >>= 1)
                #pragma unroll
                for (int i = 0; i < 16; i++)
                    if (i < st) v[i] = fmaxf(v[i], v[i + st]);
            best = v[0];
            unsigned mask = 0;
            #pragma unroll
            for (int p = 0; p < TAGS; p++)
                mask |= (sc[p] == best) ? (1u << p) : 0u;
            arg = __ffs(mask) - 1;                       // first (lowest) argmax
        }
        __syncwarp();
        if (lane < TAGS) {
            fvs[lane] = best + feat;
            bp[t * TAGS + lane] = (unsigned char)arg;
        }
        __syncwarp();
        feat = nfeat;
    }

    float term = (lane < TAGS) ? fvs[lane] + trans[STOPT * TAGS + lane] : -3.4e38f;
    int bi = lane;
    #pragma unroll
    for (int off = 16; off > 0; off >>= 1) {
        float ov = __shfl_down_sync(0xffffffff, term, off);
        int   oi = __shfl_down_sync(0xffffffff, bi,   off);
        if (ov > term || (ov == term && oi < bi)) { term = ov; bi = oi; }
    }
    term = __shfl_sync(0xffffffff, term, 0);
    bi   = __shfl_sync(0xffffffff, bi,   0);

    if (lane == 0) {
        float* po = out;
        if (out_size > TT) { out[0] = term; po = out + 1; }
        int tag = bi;
        for (int t = TT - 1; t >= 0; t--) {
            po[t] = (float)tag;
            tag = bp[t * TAGS + tag];
        }
    }
}

// ---------------- launcher ----------------
extern "C" void kernel_launch(void* const* d_in, const int* in_sizes, int n_in,
                              void* d_out, int out_size)
{
    const float* features = (const float*)d_in[0];
    const float* conv1_w  = (const float*)d_in[1];
    const float* conv1_b  = (const float*)d_in[2];
    const float* conv3_w  = (const float*)d_in[3];
    const float* conv3_b  = (const float*)d_in[4];
    const float* conv5_w  = (const float*)d_in[5];
    const float* conv5_b  = (const float*)d_in[6];
    const float* wih0f = (const float*)d_in[7];
    const float* whh0f = (const float*)d_in[8];
    const float* bih0f = (const float*)d_in[9];
    const float* bhh0f = (const float*)d_in[10];
    const float* wih0r = (const float*)d_in[11];
    const float* whh0r = (const float*)d_in[12];
    const float* bih0r = (const float*)d_in[13];
    const float* bhh0r = (const float*)d_in[14];
    const float* wih1f = (const float*)d_in[15];
    const float* whh1f = (const float*)d_in[16];
    const float* bih1f = (const float*)d_in[17];
    const float* bhh1f = (const float*)d_in[18];
    const float* wih1r = (const float*)d_in[19];
    const float* whh1r = (const float*)d_in[20];
    const float* bih1r = (const float*)d_in[21];
    const float* bhh1r = (const float*)d_in[22];
    const float* h2t_w = (const float*)d_in[23];
    const float* h2t_b = (const float*)d_in[24];
    const float* trans = (const float*)d_in[25];

    float* out = (float*)d_out;

    float* px   = nullptr; cudaGetSymbolAddress((void**)&px,   d_x);
    float* pgxf = nullptr; cudaGetSymbolAddress((void**)&pgxf, d_gxf);
    float* pgxr = nullptr; cudaGetSymbolAddress((void**)&pgxr, d_gxr);
    float* py0  = nullptr; cudaGetSymbolAddress((void**)&py0,  d_y0);
    float* py1  = nullptr; cudaGetSymbolAddress((void**)&py1,  d_y1);
    float* plog = nullptr; cudaGetSymbolAddress((void**)&plog, d_logits);

    // 1. poison mailboxes (both layers, both slots)
    zero_mail_kernel<<<1, 256>>>();

    // 2. conv features
    conv_kernel<<<TT, 128>>>(features, conv1_w, conv1_b, conv3_w, conv3_b,
                             conv5_w, conv5_b, px);

    // 3. layer 0 input-gate GEMMs (fwd + bwd)
    dim3 ggrid(GATES / 128, TT / 128, 2);
    gemm_dual_kernel<<<ggrid, 256>>>(px,
                                     wih0f, bih0f, bhh0f, pgxf,
                                     wih0r, bih0r, bhh0r, pgxr,
                                     TT, GATES, DIN);

    // 4. layer 0 recurrence
    recur_kernel<<<2 * RC_C, 256>>>(pgxf, pgxr, whh0f, whh0r, py0, 0);

    // 5. layer 1 input-gate GEMMs
    gemm_dual_kernel<<<ggrid, 256>>>(py0,
                                     wih1f, bih1f, bhh1f, pgxf,
                                     wih1r, bih1r, bhh1r, pgxr,
                                     TT, GATES, Y1DIM);

    // 6. layer 1 recurrence
    recur_kernel<<<2 * RC_C, 256>>>(pgxf, pgxr, whh1f, whh1r, py1, 1);

    // 7. tag logits
    h2t_kernel<<<(TT * 32) / 256, 256>>>(py1, h2t_w, h2t_b, plog);

    // 8. Viterbi decode + output
    const int vit_smem = TT * TAGS + 32 * sizeof(float);
    cudaFuncSetAttribute(viterbi_kernel, cudaFuncAttributeMaxDynamicSharedMemorySize, vit_smem);
    viterbi_kernel<<<1, 32, vit_smem>>>(plog, trans, out, out_size);
}